// round 5
// baseline (speedup 1.0000x reference)
#include <cuda_runtime.h>
#include <math.h>

#define NN 50000
#define EE 800000
#define HF 128          // H*F = 2*64
#define INF_ 128        // IN_FEATS

// ---------------- scratch (static device globals; no allocation) ----------------
__device__ float g_z[2u * NN * HF];      // projected features, gates u,c  (51.2 MB)
__device__ float g_gate[2u * NN * HF];   // GATConv outputs pre-bias       (51.2 MB)
__device__ float2 g_el[2 * NN];          // per-node attn-left dot, 2 heads
__device__ float2 g_er[2 * NN];          // per-node attn-right dot, 2 heads
__device__ int   g_csr_src[EE];
__device__ int   g_offsets[NN + 1];
__device__ int   g_counts[NN];
__device__ int   g_cursor[NN];

// ---------------- CSR build ----------------
__global__ void zero_kernel() {
    int i = blockIdx.x * blockDim.x + threadIdx.x;
    if (i < NN) { g_counts[i] = 0; g_cursor[i] = 0; }
}

__global__ void count_kernel(const int* __restrict__ dst) {
    int e = blockIdx.x * blockDim.x + threadIdx.x;
    if (e < EE) atomicAdd(&g_counts[dst[e]], 1);
}

// single-block scan: counts -> exclusive offsets
__global__ void scan_kernel() {
    __shared__ int warpsum[32];
    int tid = threadIdx.x, lane = tid & 31, wid = tid >> 5;
    int carry = 0;
    if (tid == 0) g_offsets[0] = 0;
    for (int base = 0; base < NN; base += 1024) {
        int i = base + tid;
        int v = (i < NN) ? g_counts[i] : 0;
        int s = v;
        #pragma unroll
        for (int off = 1; off < 32; off <<= 1) {
            int t = __shfl_up_sync(0xffffffffu, s, off);
            if (lane >= off) s += t;
        }
        if (lane == 31) warpsum[wid] = s;
        __syncthreads();
        if (wid == 0) {
            int ws = warpsum[lane];
            #pragma unroll
            for (int off = 1; off < 32; off <<= 1) {
                int t = __shfl_up_sync(0xffffffffu, ws, off);
                if (lane >= off) ws += t;
            }
            warpsum[lane] = ws;
        }
        __syncthreads();
        int prefix = (wid > 0) ? warpsum[wid - 1] : 0;
        int incl = s + prefix;
        if (i < NN) g_offsets[i + 1] = carry + incl;
        carry += warpsum[31];
        __syncthreads();
    }
}

__global__ void scatter_kernel(const int* __restrict__ src, const int* __restrict__ dst) {
    int e = blockIdx.x * blockDim.x + threadIdx.x;
    if (e < EE) {
        int d = dst[e];
        int p = g_offsets[d] + atomicAdd(&g_cursor[d], 1);
        g_csr_src[p] = src[e];
    }
}

// ---------------- GEMM: z[g][n][:] = x[n] . W[g+1][:][:]^T ----------------
// BM=128, BN=128 (full output width), K=128 in chunks of 32. 256 threads, 8x8/thread.
__global__ void __launch_bounds__(256, 2)
gemm_kernel(const float* __restrict__ x, const float* __restrict__ W) {
    __shared__ float As[128][36];  // [m][k], padded; a-reads broadcast (2 addrs/warp)
    __shared__ float Bs[32][128];  // [k][n], b-reads LDS.128 conflict-free

    const int g = blockIdx.y;                       // 0 -> W[1] (u), 1 -> W[2] (c)
    const float* Wg = W + (size_t)(g + 1) * HF * INF_;
    const int row0 = blockIdx.x * 128;
    const int t  = threadIdx.x;
    const int tx = t & 15, ty = t >> 4;
    const int tm0 = ty * 8, tn0 = tx * 8;

    float acc[8][8];
    #pragma unroll
    for (int i = 0; i < 8; i++)
        #pragma unroll
        for (int j = 0; j < 8; j++) acc[i][j] = 0.0f;

    for (int k0 = 0; k0 < INF_; k0 += 32) {
        // load A tile 128x32 (4 float4 per thread)
        #pragma unroll
        for (int r = 0; r < 4; r++) {
            int id = t + 256 * r;        // 0..1023
            int row = id >> 3;
            int kv = (id & 7) << 2;
            float4 v = make_float4(0.f, 0.f, 0.f, 0.f);
            int grow = row0 + row;
            if (grow < NN) v = *(const float4*)(x + (size_t)grow * INF_ + k0 + kv);
            *(float4*)&As[row][kv] = v;
        }
        // load B tile (W rows = output cols), transposed into Bs[k][n]
        #pragma unroll
        for (int r = 0; r < 4; r++) {
            int id = t + 256 * r;
            int j = id >> 3;
            int kv = (id & 7) << 2;
            float4 v = *(const float4*)(Wg + j * INF_ + k0 + kv);
            Bs[kv + 0][j] = v.x; Bs[kv + 1][j] = v.y;
            Bs[kv + 2][j] = v.z; Bs[kv + 3][j] = v.w;
        }
        __syncthreads();

        #pragma unroll
        for (int k = 0; k < 32; k++) {
            float a[8], b[8];
            #pragma unroll
            for (int i = 0; i < 8; i++) a[i] = As[tm0 + i][k];
            float4 b0 = *(const float4*)&Bs[k][tn0];
            float4 b1 = *(const float4*)&Bs[k][tn0 + 4];
            b[0] = b0.x; b[1] = b0.y; b[2] = b0.z; b[3] = b0.w;
            b[4] = b1.x; b[5] = b1.y; b[6] = b1.z; b[7] = b1.w;
            #pragma unroll
            for (int i = 0; i < 8; i++)
                #pragma unroll
                for (int j = 0; j < 8; j++)
                    acc[i][j] = fmaf(a[i], b[j], acc[i][j]);
        }
        __syncthreads();
    }

    // write z
    #pragma unroll
    for (int i = 0; i < 8; i++) {
        int grow = row0 + tm0 + i;
        if (grow < NN) {
            float* zp = g_z + ((size_t)g * NN + grow) * HF + tn0;
            float4 v0 = make_float4(acc[i][0], acc[i][1], acc[i][2], acc[i][3]);
            float4 v1 = make_float4(acc[i][4], acc[i][5], acc[i][6], acc[i][7]);
            *(float4*)(zp)     = v0;
            *(float4*)(zp + 4) = v1;
        }
    }
}

// ---------------- el/er: per-node attention dots ----------------
__global__ void elr_kernel(const float* __restrict__ attn_l, const float* __restrict__ attn_r) {
    int w = (blockIdx.x * blockDim.x + threadIdx.x) >> 5;
    int lane = threadIdx.x & 31;
    if (w >= NN) return;
    int n = w;
    #pragma unroll
    for (int g = 0; g < 2; g++) {
        const float* zp = g_z + ((size_t)g * NN + n) * HF;
        const float* al = attn_l + (g + 1) * HF;
        const float* ar = attn_r + (g + 1) * HF;
        float z0 = zp[lane], z1 = zp[lane + 32];
        float z2 = zp[lane + 64], z3 = zp[lane + 96];
        float el0 = z0 * __ldg(al + lane) + z1 * __ldg(al + lane + 32);
        float er0 = z0 * __ldg(ar + lane) + z1 * __ldg(ar + lane + 32);
        float el1 = z2 * __ldg(al + lane + 64) + z3 * __ldg(al + lane + 96);
        float er1 = z2 * __ldg(ar + lane + 64) + z3 * __ldg(ar + lane + 96);
        #pragma unroll
        for (int off = 16; off; off >>= 1) {
            el0 += __shfl_xor_sync(0xffffffffu, el0, off);
            er0 += __shfl_xor_sync(0xffffffffu, er0, off);
            el1 += __shfl_xor_sync(0xffffffffu, el1, off);
            er1 += __shfl_xor_sync(0xffffffffu, er1, off);
        }
        if (lane == 0) {
            g_el[g * NN + n] = make_float2(el0, el1);
            g_er[g * NN + n] = make_float2(er0, er1);
        }
    }
}

// ---------------- edge softmax + aggregation: one warp per (node, gate) ----------------
__global__ void edge_kernel() {
    int w = (blockIdx.x * blockDim.x + threadIdx.x) >> 5;
    if (w >= 2 * NN) return;
    int n = w >> 1, g = w & 1;
    int lane = threadIdx.x & 31;
    int start = g_offsets[n], end = g_offsets[n + 1];
    float* outp = g_gate + ((size_t)g * NN + n) * HF;
    if (start == end) {
        outp[lane] = 0.f; outp[lane + 32] = 0.f;
        outp[lane + 64] = 0.f; outp[lane + 96] = 0.f;
        return;
    }
    float2 erd = g_er[g * NN + n];

    // pass A: per-head max of leaky_relu(el[src]+er[dst])
    float m0 = -1e30f, m1 = -1e30f;
    for (int i = start + lane; i < end; i += 32) {
        int s = g_csr_src[i];
        float2 els = g_el[g * NN + s];
        float e0 = els.x + erd.x; e0 = (e0 > 0.f) ? e0 : 0.2f * e0;
        float e1 = els.y + erd.y; e1 = (e1 > 0.f) ? e1 : 0.2f * e1;
        m0 = fmaxf(m0, e0); m1 = fmaxf(m1, e1);
    }
    #pragma unroll
    for (int off = 16; off; off >>= 1) {
        m0 = fmaxf(m0, __shfl_xor_sync(0xffffffffu, m0, off));
        m1 = fmaxf(m1, __shfl_xor_sync(0xffffffffu, m1, off));
    }

    // pass B: exp-weighted accumulation of z[src]
    float a00 = 0.f, a01 = 0.f, a10 = 0.f, a11 = 0.f, s0 = 0.f, s1 = 0.f;
    for (int base = start; base < end; base += 32) {
        int i = base + lane;
        int sid = 0; float w0 = 0.f, w1 = 0.f;
        if (i < end) {
            sid = g_csr_src[i];
            float2 els = g_el[g * NN + sid];
            float e0 = els.x + erd.x; e0 = (e0 > 0.f) ? e0 : 0.2f * e0;
            float e1 = els.y + erd.y; e1 = (e1 > 0.f) ? e1 : 0.2f * e1;
            w0 = __expf(e0 - m0); w1 = __expf(e1 - m1);
        }
        int cnt = min(32, end - base);
        for (int j = 0; j < cnt; j++) {
            int sj   = __shfl_sync(0xffffffffu, sid, j);
            float wj0 = __shfl_sync(0xffffffffu, w0, j);
            float wj1 = __shfl_sync(0xffffffffu, w1, j);
            const float* zp = g_z + ((size_t)g * NN + sj) * HF;
            float z00 = zp[lane], z01 = zp[lane + 32];
            float z10 = zp[lane + 64], z11 = zp[lane + 96];
            a00 = fmaf(wj0, z00, a00); a01 = fmaf(wj0, z01, a01);
            a10 = fmaf(wj1, z10, a10); a11 = fmaf(wj1, z11, a11);
            s0 += wj0; s1 += wj1;
        }
    }
    float inv0 = 1.0f / s0, inv1 = 1.0f / s1;
    outp[lane]      = a00 * inv0;
    outp[lane + 32] = a01 * inv0;
    outp[lane + 64] = a10 * inv1;
    outp[lane + 96] = a11 * inv1;
}

// ---------------- final: sigmoids + gated combine ----------------
__global__ void final_kernel(const float* __restrict__ h,
                             const float* __restrict__ conv_bias,
                             const float* __restrict__ gate_bias,
                             float* __restrict__ out) {
    int idx = blockIdx.x * blockDim.x + threadIdx.x;
    if (idx >= NN * HF) return;
    int hf = idx & (HF - 1);
    float bu = __ldg(conv_bias + 1 * HF + hf) + __ldg(gate_bias + 1 * HF + hf);
    float bc = __ldg(conv_bias + 2 * HF + hf) + __ldg(gate_bias + 2 * HF + hf);
    float u = 1.0f / (1.0f + __expf(-(g_gate[idx] + bu)));
    float c = 1.0f / (1.0f + __expf(-(g_gate[(size_t)NN * HF + idx] + bc)));
    out[idx] = u * h[idx] + (1.0f - u) * c;
}

// ---------------- launch ----------------
extern "C" void kernel_launch(void* const* d_in, const int* in_sizes, int n_in,
                              void* d_out, int out_size) {
    const float* x         = (const float*)d_in[0];
    const float* h         = (const float*)d_in[1];
    const float* W         = (const float*)d_in[2];
    const float* attn_l    = (const float*)d_in[3];
    const float* attn_r    = (const float*)d_in[4];
    const float* conv_bias = (const float*)d_in[5];
    const float* gate_bias = (const float*)d_in[6];
    const int*   src       = (const int*)d_in[7];
    const int*   dst       = (const int*)d_in[8];
    float* out = (float*)d_out;

    zero_kernel<<<(NN + 255) / 256, 256>>>();
    count_kernel<<<(EE + 511) / 512, 512>>>(dst);
    scan_kernel<<<1, 1024>>>();
    scatter_kernel<<<(EE + 511) / 512, 512>>>(src, dst);

    gemm_kernel<<<dim3((NN + 127) / 128, 2), 256>>>(x, W);
    elr_kernel<<<(NN * 32 + 255) / 256, 256>>>(attn_l, attn_r);
    edge_kernel<<<(2 * NN * 32 + 255) / 256, 256>>>();
    final_kernel<<<(NN * HF + 255) / 256, 256>>>(h, conv_bias, gate_bias, out);
}

// round 9
// speedup vs baseline: 1.4827x; 1.4827x over previous
#include <cuda_runtime.h>
#include <math.h>
#include <stdint.h>

#define NN 50000
#define EE 800000
#define HF 128          // H*F = 2*64
#define INF_ 128        // IN_FEATS
#define SCAN_B 512
#define NBLK ((NN + SCAN_B - 1) / SCAN_B)   // 98

// ---------------- scratch (static device globals; no allocation) ----------------
__device__ float g_z[2u * NN * HF];      // projected features, gates u,c
__device__ float g_gate[2u * NN * HF];   // GATConv outputs pre-bias
__device__ float2 g_el[2 * NN];
__device__ float2 g_er[2 * NN];
__device__ int   g_csr_src[EE];
__device__ int   g_offsets[NN + 1];
__device__ int   g_counts[NN];
__device__ int   g_cursor[NN];
__device__ int   g_blocksum[NBLK];

// ---------------- CSR build ----------------
__global__ void zero_kernel() {
    int i = blockIdx.x * blockDim.x + threadIdx.x;
    if (i < NN) g_counts[i] = 0;
}

__global__ void count_kernel(const int* __restrict__ dst) {
    int e = blockIdx.x * blockDim.x + threadIdx.x;
    if (e < EE) atomicAdd(&g_counts[dst[e]], 1);
}

// scan stage 1: per-block sums of counts
__global__ void scan1_kernel() {
    __shared__ int wsum[16];
    int b = blockIdx.x, t = threadIdx.x;
    int lane = t & 31, w = t >> 5;
    int i = b * SCAN_B + t;
    int v = (i < NN) ? g_counts[i] : 0;
    #pragma unroll
    for (int off = 16; off; off >>= 1) v += __shfl_xor_sync(0xffffffffu, v, off);
    if (lane == 0) wsum[w] = v;
    __syncthreads();
    if (t == 0) {
        int s = 0;
        #pragma unroll
        for (int k = 0; k < 16; k++) s += wsum[k];
        g_blocksum[b] = s;
    }
}

// scan stage 2: exclusive scan of the 98 block sums (1 block, 128 threads)
__global__ void scan2_kernel() {
    __shared__ int ws[4];
    int t = threadIdx.x;
    int lane = t & 31, w = t >> 5;
    int v = (t < NBLK) ? g_blocksum[t] : 0;
    int s = v;
    #pragma unroll
    for (int off = 1; off < 32; off <<= 1) {
        int tmp = __shfl_up_sync(0xffffffffu, s, off);
        if (lane >= off) s += tmp;
    }
    if (lane == 31) ws[w] = s;
    __syncthreads();
    if (t == 0) {
        int a = 0;
        #pragma unroll
        for (int k = 0; k < 4; k++) { int tmp = ws[k]; ws[k] = a; a += tmp; }
    }
    __syncthreads();
    int incl = s + ws[w];
    if (t < NBLK) g_blocksum[t] = incl - v;   // exclusive block base
}

// scan stage 3: per-block inclusive scan + block base -> offsets; also reset cursor
__global__ void scan3_kernel() {
    __shared__ int wsum[16];
    int b = blockIdx.x, t = threadIdx.x;
    int lane = t & 31, w = t >> 5;
    int i = b * SCAN_B + t;
    int v = (i < NN) ? g_counts[i] : 0;
    int s = v;
    #pragma unroll
    for (int off = 1; off < 32; off <<= 1) {
        int tmp = __shfl_up_sync(0xffffffffu, s, off);
        if (lane >= off) s += tmp;
    }
    if (lane == 31) wsum[w] = s;
    __syncthreads();
    if (w == 0 && lane < 16) {
        int ws_ = wsum[lane];
        #pragma unroll
        for (int off = 1; off < 16; off <<= 1) {
            int tmp = __shfl_up_sync(0x0000ffffu, ws_, off);
            if (lane >= off) ws_ += tmp;
        }
        wsum[lane] = ws_;
    }
    __syncthreads();
    int prefix = (w > 0) ? wsum[w - 1] : 0;
    int incl = s + prefix + g_blocksum[b];
    if (i < NN) {
        g_offsets[i + 1] = incl;
        g_cursor[i] = 0;
    }
    if (b == 0 && t == 0) g_offsets[0] = 0;
}

__global__ void scatter_kernel(const int* __restrict__ src, const int* __restrict__ dst) {
    int e = blockIdx.x * blockDim.x + threadIdx.x;
    if (e < EE) {
        int d = dst[e];
        int p = g_offsets[d] + atomicAdd(&g_cursor[d], 1);
        g_csr_src[p] = src[e];
    }
}

// ---------------- tf32 tensor-core GEMM ----------------
__device__ __forceinline__ float to_tf32(float x) {
    uint32_t u;
    asm("cvt.rna.tf32.f32 %0, %1;" : "=r"(u) : "f"(x));
    return __uint_as_float(u);
}

__device__ __forceinline__ void mma_tf32(float c[4], const uint32_t a[4], const uint32_t b[2]) {
    asm volatile(
        "mma.sync.aligned.m16n8k8.row.col.f32.tf32.tf32.f32 "
        "{%0,%1,%2,%3}, {%4,%5,%6,%7}, {%8,%9}, {%0,%1,%2,%3};"
        : "+f"(c[0]), "+f"(c[1]), "+f"(c[2]), "+f"(c[3])
        : "r"(a[0]), "r"(a[1]), "r"(a[2]), "r"(a[3]), "r"(b[0]), "r"(b[1]));
}

// BM=128, BN=128 (full HF), BK=32, 256 threads = 8 warps (4 m x 2 n).
// Warp tile 32x64 = 2 m16-tiles x 8 n8-tiles.
__global__ void __launch_bounds__(256)
gemm_kernel(const float* __restrict__ x, const float* __restrict__ W) {
    __shared__ float As[128][36];   // pad 36: conflict-bounded frag reads
    __shared__ float Bs[128][36];   // Bs[n][k] == B col-major (K x N)

    const int g = blockIdx.y;                       // 0 -> W[1] (u), 1 -> W[2] (c)
    const float* Wg = W + (size_t)(g + 1) * HF * INF_;
    const int row0 = blockIdx.x * 128;
    const int t = threadIdx.x;
    const int lane = t & 31, wid = t >> 5;
    const int warp_m = wid >> 1, warp_n = wid & 1;

    float c[2][8][4];
    #pragma unroll
    for (int mi = 0; mi < 2; mi++)
        #pragma unroll
        for (int ni = 0; ni < 8; ni++)
            #pragma unroll
            for (int q = 0; q < 4; q++) c[mi][ni][q] = 0.0f;

    for (int k0 = 0; k0 < INF_; k0 += 32) {
        #pragma unroll
        for (int r = 0; r < 4; r++) {
            int id = t + 256 * r;          // 0..1023
            int row = id >> 3;             // 0..127
            int kv = (id & 7) << 2;        // 0,4,...,28
            float4 v = make_float4(0.f, 0.f, 0.f, 0.f);
            int gr = row0 + row;
            if (gr < NN) v = *(const float4*)(x + (size_t)gr * INF_ + k0 + kv);
            As[row][kv + 0] = to_tf32(v.x);
            As[row][kv + 1] = to_tf32(v.y);
            As[row][kv + 2] = to_tf32(v.z);
            As[row][kv + 3] = to_tf32(v.w);
            float4 w4 = *(const float4*)(Wg + row * INF_ + k0 + kv);
            Bs[row][kv + 0] = to_tf32(w4.x);
            Bs[row][kv + 1] = to_tf32(w4.y);
            Bs[row][kv + 2] = to_tf32(w4.z);
            Bs[row][kv + 3] = to_tf32(w4.w);
        }
        __syncthreads();

        #pragma unroll
        for (int kk = 0; kk < 32; kk += 8) {
            uint32_t af[2][4], bf[8][2];
            const int ac = kk + (lane & 3);
            #pragma unroll
            for (int mi = 0; mi < 2; mi++) {
                int ar = warp_m * 32 + mi * 16 + (lane >> 2);
                af[mi][0] = __float_as_uint(As[ar][ac]);
                af[mi][1] = __float_as_uint(As[ar + 8][ac]);
                af[mi][2] = __float_as_uint(As[ar][ac + 4]);
                af[mi][3] = __float_as_uint(As[ar + 8][ac + 4]);
            }
            #pragma unroll
            for (int ni = 0; ni < 8; ni++) {
                int br = warp_n * 64 + ni * 8 + (lane >> 2);
                bf[ni][0] = __float_as_uint(Bs[br][ac]);
                bf[ni][1] = __float_as_uint(Bs[br][ac + 4]);
            }
            #pragma unroll
            for (int mi = 0; mi < 2; mi++)
                #pragma unroll
                for (int ni = 0; ni < 8; ni++)
                    mma_tf32(c[mi][ni], af[mi], bf[ni]);
        }
        __syncthreads();
    }

    // epilogue: c0=C[r][cc], c1=C[r][cc+1], c2=C[r+8][cc], c3=C[r+8][cc+1]
    #pragma unroll
    for (int mi = 0; mi < 2; mi++) {
        int rbase = row0 + warp_m * 32 + mi * 16 + (lane >> 2);
        #pragma unroll
        for (int half = 0; half < 2; half++) {
            int rr = rbase + half * 8;
            if (rr < NN) {
                float* zp = g_z + ((size_t)g * NN + rr) * HF;
                #pragma unroll
                for (int ni = 0; ni < 8; ni++) {
                    int cc = warp_n * 64 + ni * 8 + (lane & 3) * 2;
                    float2 v = half ? make_float2(c[mi][ni][2], c[mi][ni][3])
                                    : make_float2(c[mi][ni][0], c[mi][ni][1]);
                    *(float2*)(zp + cc) = v;
                }
            }
        }
    }
}

// ---------------- el/er: per-node attention dots ----------------
__global__ void elr_kernel(const float* __restrict__ attn_l, const float* __restrict__ attn_r) {
    int w = (blockIdx.x * blockDim.x + threadIdx.x) >> 5;
    int lane = threadIdx.x & 31;
    if (w >= NN) return;
    int n = w;
    #pragma unroll
    for (int g = 0; g < 2; g++) {
        const float* zp = g_z + ((size_t)g * NN + n) * HF;
        const float* al = attn_l + (g + 1) * HF;
        const float* ar = attn_r + (g + 1) * HF;
        float z0 = zp[lane], z1 = zp[lane + 32];
        float z2 = zp[lane + 64], z3 = zp[lane + 96];
        float el0 = z0 * __ldg(al + lane) + z1 * __ldg(al + lane + 32);
        float er0 = z0 * __ldg(ar + lane) + z1 * __ldg(ar + lane + 32);
        float el1 = z2 * __ldg(al + lane + 64) + z3 * __ldg(al + lane + 96);
        float er1 = z2 * __ldg(ar + lane + 64) + z3 * __ldg(ar + lane + 96);
        #pragma unroll
        for (int off = 16; off; off >>= 1) {
            el0 += __shfl_xor_sync(0xffffffffu, el0, off);
            er0 += __shfl_xor_sync(0xffffffffu, er0, off);
            el1 += __shfl_xor_sync(0xffffffffu, el1, off);
            er1 += __shfl_xor_sync(0xffffffffu, er1, off);
        }
        if (lane == 0) {
            g_el[g * NN + n] = make_float2(el0, el1);
            g_er[g * NN + n] = make_float2(er0, er1);
        }
    }
}

// ---------------- edge softmax + aggregation: one warp per (node, gate) ----------------
// float4 gather: lane L owns cols [4L, 4L+4); lanes 0-15 = head0, 16-31 = head1.
__global__ void edge_kernel() {
    int w = (blockIdx.x * blockDim.x + threadIdx.x) >> 5;
    if (w >= 2 * NN) return;
    int n = w >> 1, g = w & 1;
    int lane = threadIdx.x & 31;
    int start = g_offsets[n], end = g_offsets[n + 1];
    float* outp = g_gate + ((size_t)g * NN + n) * HF;
    if (start == end) {
        *(float4*)(outp + lane * 4) = make_float4(0.f, 0.f, 0.f, 0.f);
        return;
    }
    float2 erd = g_er[g * NN + n];

    // pass A: per-head max of leaky_relu(el[src]+er[dst])
    float m0 = -1e30f, m1 = -1e30f;
    for (int i = start + lane; i < end; i += 32) {
        int s = g_csr_src[i];
        float2 els = g_el[g * NN + s];
        float e0 = els.x + erd.x; e0 = (e0 > 0.f) ? e0 : 0.2f * e0;
        float e1 = els.y + erd.y; e1 = (e1 > 0.f) ? e1 : 0.2f * e1;
        m0 = fmaxf(m0, e0); m1 = fmaxf(m1, e1);
    }
    #pragma unroll
    for (int off = 16; off; off >>= 1) {
        m0 = fmaxf(m0, __shfl_xor_sync(0xffffffffu, m0, off));
        m1 = fmaxf(m1, __shfl_xor_sync(0xffffffffu, m1, off));
    }

    // pass B: exp-weighted accumulation of z[src]
    float4 acc = make_float4(0.f, 0.f, 0.f, 0.f);
    float s0 = 0.f, s1 = 0.f;
    for (int base = start; base < end; base += 32) {
        int i = base + lane;
        int sid = 0; float w0 = 0.f, w1 = 0.f;
        if (i < end) {
            sid = g_csr_src[i];
            float2 els = g_el[g * NN + sid];
            float e0 = els.x + erd.x; e0 = (e0 > 0.f) ? e0 : 0.2f * e0;
            float e1 = els.y + erd.y; e1 = (e1 > 0.f) ? e1 : 0.2f * e1;
            w0 = __expf(e0 - m0); w1 = __expf(e1 - m1);
        }
        int cnt = min(32, end - base);
        for (int j = 0; j < cnt; j++) {
            int sj    = __shfl_sync(0xffffffffu, sid, j);
            float wj0 = __shfl_sync(0xffffffffu, w0, j);
            float wj1 = __shfl_sync(0xffffffffu, w1, j);
            const float4 zv = *(const float4*)(g_z + ((size_t)g * NN + sj) * HF + lane * 4);
            float wj = (lane < 16) ? wj0 : wj1;
            acc.x = fmaf(wj, zv.x, acc.x);
            acc.y = fmaf(wj, zv.y, acc.y);
            acc.z = fmaf(wj, zv.z, acc.z);
            acc.w = fmaf(wj, zv.w, acc.w);
            s0 += wj0; s1 += wj1;
        }
    }
    float inv = 1.0f / ((lane < 16) ? s0 : s1);
    acc.x *= inv; acc.y *= inv; acc.z *= inv; acc.w *= inv;
    *(float4*)(outp + lane * 4) = acc;
}

// ---------------- final: sigmoids + gated combine ----------------
__global__ void final_kernel(const float* __restrict__ h,
                             const float* __restrict__ conv_bias,
                             const float* __restrict__ gate_bias,
                             float* __restrict__ out) {
    int idx = blockIdx.x * blockDim.x + threadIdx.x;
    if (idx >= NN * HF) return;
    int hf = idx & (HF - 1);
    float bu = __ldg(conv_bias + 1 * HF + hf) + __ldg(gate_bias + 1 * HF + hf);
    float bc = __ldg(conv_bias + 2 * HF + hf) + __ldg(gate_bias + 2 * HF + hf);
    float u = 1.0f / (1.0f + __expf(-(g_gate[idx] + bu)));
    float c = 1.0f / (1.0f + __expf(-(g_gate[(size_t)NN * HF + idx] + bc)));
    out[idx] = u * h[idx] + (1.0f - u) * c;
}

// ---------------- launch ----------------
extern "C" void kernel_launch(void* const* d_in, const int* in_sizes, int n_in,
                              void* d_out, int out_size) {
    const float* x         = (const float*)d_in[0];
    const float* h         = (const float*)d_in[1];
    const float* W         = (const float*)d_in[2];
    const float* attn_l    = (const float*)d_in[3];
    const float* attn_r    = (const float*)d_in[4];
    const float* conv_bias = (const float*)d_in[5];
    const float* gate_bias = (const float*)d_in[6];
    const int*   src       = (const int*)d_in[7];
    const int*   dst       = (const int*)d_in[8];
    float* out = (float*)d_out;

    zero_kernel<<<(NN + 255) / 256, 256>>>();
    count_kernel<<<(EE + 511) / 512, 512>>>(dst);
    scan1_kernel<<<NBLK, SCAN_B>>>();
    scan2_kernel<<<1, 128>>>();
    scan3_kernel<<<NBLK, SCAN_B>>>();
    scatter_kernel<<<(EE + 511) / 512, 512>>>(src, dst);

    gemm_kernel<<<dim3((NN + 127) / 128, 2), 256>>>(x, W);
    elr_kernel<<<(NN * 32 + 255) / 256, 256>>>(attn_l, attn_r);
    edge_kernel<<<(2 * NN * 32 + 255) / 256, 256>>>();
    final_kernel<<<(NN * HF + 255) / 256, 256>>>(h, conv_bias, gate_bias, out);
}

// round 11
// speedup vs baseline: 2.0248x; 1.3656x over previous
#include <cuda_runtime.h>
#include <cuda_fp16.h>
#include <math.h>
#include <stdint.h>

#define NN 50000
#define EE 800000
#define HF 128          // H*F = 2*64
#define INF_ 128        // IN_FEATS
#define SCAN_B 512
#define NBLK ((NN + SCAN_B - 1) / SCAN_B)   // 98

// ---------------- scratch (static device globals; no allocation) ----------------
__device__ __half g_zh[2u * NN * HF];    // half-precision z (messages), 25.6 MB
__device__ float4 g_el4[NN];             // (g0h0, g0h1, g1h0, g1h1)
__device__ float4 g_er4[NN];
__device__ int    g_csr_src[EE];
__device__ int    g_offsets[NN + 1];
__device__ int    g_counts[NN];
__device__ int    g_cursor[NN];
__device__ int    g_blocksum[NBLK];
__device__ int    g_scan_done = 0;

// ---------------- CSR build ----------------
__global__ void zero_kernel() {
    int i = blockIdx.x * blockDim.x + threadIdx.x;
    if (i < NN) g_counts[i] = 0;
}

__global__ void count_kernel(const int* __restrict__ dst) {
    int e = blockIdx.x * blockDim.x + threadIdx.x;
    if (e < EE) atomicAdd(&g_counts[dst[e]], 1);
}

// fused scan stage 1+2: per-block sums; LAST block scans the 98 block sums.
__global__ void scan12_kernel() {
    __shared__ int wsum[16];
    __shared__ int ws2[4];
    __shared__ int is_last;
    int b = blockIdx.x, t = threadIdx.x;
    int lane = t & 31, w = t >> 5;
    int i = b * SCAN_B + t;
    int v = (i < NN) ? g_counts[i] : 0;
    #pragma unroll
    for (int off = 16; off; off >>= 1) v += __shfl_xor_sync(0xffffffffu, v, off);
    if (lane == 0) wsum[w] = v;
    __syncthreads();
    if (t == 0) {
        int s = 0;
        #pragma unroll
        for (int k = 0; k < 16; k++) s += wsum[k];
        g_blocksum[b] = s;
        __threadfence();
        int prev = atomicAdd(&g_scan_done, 1);
        is_last = (prev == gridDim.x - 1);
    }
    __syncthreads();
    if (is_last) {
        int ss = 0, vv = 0;
        if (t < 128) {
            int lane2 = t & 31, w2 = t >> 5;
            vv = (t < NBLK) ? g_blocksum[t] : 0;
            ss = vv;
            #pragma unroll
            for (int off = 1; off < 32; off <<= 1) {
                int tmp = __shfl_up_sync(0xffffffffu, ss, off);
                if (lane2 >= off) ss += tmp;
            }
            if (lane2 == 31) ws2[w2] = ss;
        }
        __syncthreads();
        if (t == 0) {
            int a = 0;
            #pragma unroll
            for (int k = 0; k < 4; k++) { int tmp = ws2[k]; ws2[k] = a; a += tmp; }
            g_scan_done = 0;   // reset for next invocation (determinism)
        }
        __syncthreads();
        if (t < 128 && t < NBLK) g_blocksum[t] = ss + ws2[t >> 5] - vv;  // exclusive base
    }
}

// scan stage 3: per-block inclusive scan + block base -> offsets; reset cursor
__global__ void scan3_kernel() {
    __shared__ int wsum[16];
    int b = blockIdx.x, t = threadIdx.x;
    int lane = t & 31, w = t >> 5;
    int i = b * SCAN_B + t;
    int v = (i < NN) ? g_counts[i] : 0;
    int s = v;
    #pragma unroll
    for (int off = 1; off < 32; off <<= 1) {
        int tmp = __shfl_up_sync(0xffffffffu, s, off);
        if (lane >= off) s += tmp;
    }
    if (lane == 31) wsum[w] = s;
    __syncthreads();
    if (w == 0 && lane < 16) {
        int ws_ = wsum[lane];
        #pragma unroll
        for (int off = 1; off < 16; off <<= 1) {
            int tmp = __shfl_up_sync(0x0000ffffu, ws_, off);
            if (lane >= off) ws_ += tmp;
        }
        wsum[lane] = ws_;
    }
    __syncthreads();
    int prefix = (w > 0) ? wsum[w - 1] : 0;
    int incl = s + prefix + g_blocksum[b];
    if (i < NN) {
        g_offsets[i + 1] = incl;
        g_cursor[i] = 0;
    }
    if (b == 0 && t == 0) g_offsets[0] = 0;
}

__global__ void scatter_kernel(const int* __restrict__ src, const int* __restrict__ dst) {
    int e = blockIdx.x * blockDim.x + threadIdx.x;
    if (e < EE) {
        int d = dst[e];
        int p = g_offsets[d] + atomicAdd(&g_cursor[d], 1);
        g_csr_src[p] = src[e];
    }
}

// ---------------- tf32 tensor-core GEMM + fused el/er + half-z store ----------------
__device__ __forceinline__ float to_tf32(float x) {
    uint32_t u;
    asm("cvt.rna.tf32.f32 %0, %1;" : "=r"(u) : "f"(x));
    return __uint_as_float(u);
}

__device__ __forceinline__ void mma_tf32(float c[4], const uint32_t a[4], const uint32_t b[2]) {
    asm volatile(
        "mma.sync.aligned.m16n8k8.row.col.f32.tf32.tf32.f32 "
        "{%0,%1,%2,%3}, {%4,%5,%6,%7}, {%8,%9}, {%0,%1,%2,%3};"
        : "+f"(c[0]), "+f"(c[1]), "+f"(c[2]), "+f"(c[3])
        : "r"(a[0]), "r"(a[1]), "r"(a[2]), "r"(a[3]), "r"(b[0]), "r"(b[1]));
}

// BM=128, BN=128, BK=32, 256 threads = 8 warps (4 m x 2 n). Warp tile 32x64.
__global__ void __launch_bounds__(256)
gemm_kernel(const float* __restrict__ x, const float* __restrict__ W,
            const float* __restrict__ attn_l, const float* __restrict__ attn_r) {
    __shared__ float As[128][36];
    __shared__ float Bs[128][36];

    const int g = blockIdx.y;                       // 0 -> W[1] (u), 1 -> W[2] (c)
    const float* Wg = W + (size_t)(g + 1) * HF * INF_;
    const int row0 = blockIdx.x * 128;
    const int t = threadIdx.x;
    const int lane = t & 31, wid = t >> 5;
    const int warp_m = wid >> 1, warp_n = wid & 1;

    float c[2][8][4];
    #pragma unroll
    for (int mi = 0; mi < 2; mi++)
        #pragma unroll
        for (int ni = 0; ni < 8; ni++)
            #pragma unroll
            for (int q = 0; q < 4; q++) c[mi][ni][q] = 0.0f;

    for (int k0 = 0; k0 < INF_; k0 += 32) {
        #pragma unroll
        for (int r = 0; r < 4; r++) {
            int id = t + 256 * r;
            int row = id >> 3;
            int kv = (id & 7) << 2;
            float4 v = make_float4(0.f, 0.f, 0.f, 0.f);
            int gr = row0 + row;
            if (gr < NN) v = *(const float4*)(x + (size_t)gr * INF_ + k0 + kv);
            As[row][kv + 0] = to_tf32(v.x);
            As[row][kv + 1] = to_tf32(v.y);
            As[row][kv + 2] = to_tf32(v.z);
            As[row][kv + 3] = to_tf32(v.w);
            float4 w4 = *(const float4*)(Wg + row * INF_ + k0 + kv);
            Bs[row][kv + 0] = to_tf32(w4.x);
            Bs[row][kv + 1] = to_tf32(w4.y);
            Bs[row][kv + 2] = to_tf32(w4.z);
            Bs[row][kv + 3] = to_tf32(w4.w);
        }
        __syncthreads();

        #pragma unroll
        for (int kk = 0; kk < 32; kk += 8) {
            uint32_t af[2][4], bf[8][2];
            const int ac = kk + (lane & 3);
            #pragma unroll
            for (int mi = 0; mi < 2; mi++) {
                int ar = warp_m * 32 + mi * 16 + (lane >> 2);
                af[mi][0] = __float_as_uint(As[ar][ac]);
                af[mi][1] = __float_as_uint(As[ar + 8][ac]);
                af[mi][2] = __float_as_uint(As[ar][ac + 4]);
                af[mi][3] = __float_as_uint(As[ar + 8][ac + 4]);
            }
            #pragma unroll
            for (int ni = 0; ni < 8; ni++) {
                int br = warp_n * 64 + ni * 8 + (lane >> 2);
                bf[ni][0] = __float_as_uint(Bs[br][ac]);
                bf[ni][1] = __float_as_uint(Bs[br][ac + 4]);
            }
            #pragma unroll
            for (int mi = 0; mi < 2; mi++)
                #pragma unroll
                for (int ni = 0; ni < 8; ni++)
                    mma_tf32(c[mi][ni], af[mi], bf[ni]);
        }
        __syncthreads();
    }

    // epilogue: store half z + compute el/er (head = warp_n) via quad reduction
    const float* al = attn_l + (g + 1) * HF;
    const float* ar = attn_r + (g + 1) * HF;
    #pragma unroll
    for (int mi = 0; mi < 2; mi++) {
        #pragma unroll
        for (int half = 0; half < 2; half++) {
            int rr = row0 + warp_m * 32 + mi * 16 + (lane >> 2) + half * 8;
            float elp = 0.f, erp = 0.f;
            if (rr < NN) {
                __half* zp = g_zh + ((size_t)g * NN + rr) * HF;
                #pragma unroll
                for (int ni = 0; ni < 8; ni++) {
                    int cc = warp_n * 64 + ni * 8 + (lane & 3) * 2;
                    float cx = half ? c[mi][ni][2] : c[mi][ni][0];
                    float cy = half ? c[mi][ni][3] : c[mi][ni][1];
                    *(half2*)(zp + cc) = __floats2half2_rn(cx, cy);
                    elp = fmaf(cx, __ldg(al + cc), fmaf(cy, __ldg(al + cc + 1), elp));
                    erp = fmaf(cx, __ldg(ar + cc), fmaf(cy, __ldg(ar + cc + 1), erp));
                }
            }
            elp += __shfl_xor_sync(0xffffffffu, elp, 1);
            elp += __shfl_xor_sync(0xffffffffu, elp, 2);
            erp += __shfl_xor_sync(0xffffffffu, erp, 1);
            erp += __shfl_xor_sync(0xffffffffu, erp, 2);
            if ((lane & 3) == 0 && rr < NN) {
                ((float*)g_el4)[(size_t)rr * 4 + g * 2 + warp_n] = elp;
                ((float*)g_er4)[(size_t)rr * 4 + g * 2 + warp_n] = erp;
            }
        }
    }
}

// ---------------- fused edge softmax-aggregate + sigmoid combine ----------------
// One warp per node, both gates. Online softmax (leaky_relu monotonic => exact).
// Lane L owns cols [4L, 4L+4); lanes 0-15 = head0, 16-31 = head1.
__global__ void __launch_bounds__(256)
edge_final_kernel(const float* __restrict__ h,
                  const float* __restrict__ conv_bias,
                  const float* __restrict__ gate_bias,
                  float* __restrict__ out) {
    int n = (blockIdx.x * blockDim.x + threadIdx.x) >> 5;
    if (n >= NN) return;
    int lane = threadIdx.x & 31;
    int hf = lane * 4;

    float4 cbu = *(const float4*)(conv_bias + HF + hf);
    float4 gbu = *(const float4*)(gate_bias + HF + hf);
    float4 cbc = *(const float4*)(conv_bias + 2 * HF + hf);
    float4 gbc = *(const float4*)(gate_bias + 2 * HF + hf);
    float bu0 = cbu.x + gbu.x, bu1 = cbu.y + gbu.y, bu2 = cbu.z + gbu.z, bu3 = cbu.w + gbu.w;
    float bc0 = cbc.x + gbc.x, bc1 = cbc.y + gbc.y, bc2 = cbc.z + gbc.z, bc3 = cbc.w + gbc.w;

    int start = g_offsets[n], end = g_offsets[n + 1];
    float a00 = 0.f, a01 = 0.f, a02 = 0.f, a03 = 0.f;   // gate u
    float a10 = 0.f, a11 = 0.f, a12 = 0.f, a13 = 0.f;   // gate c
    float s0 = 0.f, s1 = 0.f, s2 = 0.f, s3 = 0.f;

    if (start < end) {
        float4 ern = g_er4[n];
        float m0 = -1e30f, m1 = -1e30f, m2 = -1e30f, m3 = -1e30f;
        for (int base = start; base < end; base += 32) {
            int i = base + lane;
            int sid = 0;
            float e0 = -1e30f, e1 = -1e30f, e2 = -1e30f, e3 = -1e30f;
            if (i < end) {
                sid = g_csr_src[i];
                float4 els = g_el4[sid];
                e0 = els.x + ern.x; e0 = (e0 > 0.f) ? e0 : 0.2f * e0;
                e1 = els.y + ern.y; e1 = (e1 > 0.f) ? e1 : 0.2f * e1;
                e2 = els.z + ern.z; e2 = (e2 > 0.f) ? e2 : 0.2f * e2;
                e3 = els.w + ern.w; e3 = (e3 > 0.f) ? e3 : 0.2f * e3;
            }
            // batch max per component
            float b0 = e0, b1 = e1, b2 = e2, b3 = e3;
            #pragma unroll
            for (int off = 16; off; off >>= 1) {
                b0 = fmaxf(b0, __shfl_xor_sync(0xffffffffu, b0, off));
                b1 = fmaxf(b1, __shfl_xor_sync(0xffffffffu, b1, off));
                b2 = fmaxf(b2, __shfl_xor_sync(0xffffffffu, b2, off));
                b3 = fmaxf(b3, __shfl_xor_sync(0xffffffffu, b3, off));
            }
            float n0 = fmaxf(m0, b0), n1 = fmaxf(m1, b1);
            float n2 = fmaxf(m2, b2), n3 = fmaxf(m3, b3);
            float sc0 = __expf(m0 - n0), sc1 = __expf(m1 - n1);
            float sc2 = __expf(m2 - n2), sc3 = __expf(m3 - n3);
            float scA = (lane < 16) ? sc0 : sc1;
            float scB = (lane < 16) ? sc2 : sc3;
            a00 *= scA; a01 *= scA; a02 *= scA; a03 *= scA;
            a10 *= scB; a11 *= scB; a12 *= scB; a13 *= scB;
            s0 *= sc0; s1 *= sc1; s2 *= sc2; s3 *= sc3;
            m0 = n0; m1 = n1; m2 = n2; m3 = n3;

            float w0 = __expf(e0 - m0), w1 = __expf(e1 - m1);
            float w2 = __expf(e2 - m2), w3 = __expf(e3 - m3);   // OOB lanes: exp(-huge)=0

            int cnt = min(32, end - base);
            for (int j = 0; j < cnt; j++) {
                int   sj  = __shfl_sync(0xffffffffu, sid, j);
                float wj0 = __shfl_sync(0xffffffffu, w0, j);
                float wj1 = __shfl_sync(0xffffffffu, w1, j);
                float wj2 = __shfl_sync(0xffffffffu, w2, j);
                float wj3 = __shfl_sync(0xffffffffu, w3, j);
                const uint2* z0 = (const uint2*)(g_zh + (size_t)sj * HF);
                const uint2* z1 = (const uint2*)(g_zh + ((size_t)NN + sj) * HF);
                uint2 q0 = z0[lane], q1 = z1[lane];
                float2 f00 = __half22float2(*(half2*)&q0.x);
                float2 f01 = __half22float2(*(half2*)&q0.y);
                float2 f10 = __half22float2(*(half2*)&q1.x);
                float2 f11 = __half22float2(*(half2*)&q1.y);
                float wA = (lane < 16) ? wj0 : wj1;
                float wB = (lane < 16) ? wj2 : wj3;
                a00 = fmaf(wA, f00.x, a00); a01 = fmaf(wA, f00.y, a01);
                a02 = fmaf(wA, f01.x, a02); a03 = fmaf(wA, f01.y, a03);
                a10 = fmaf(wB, f10.x, a10); a11 = fmaf(wB, f10.y, a11);
                a12 = fmaf(wB, f11.x, a12); a13 = fmaf(wB, f11.y, a13);
                s0 += wj0; s1 += wj1; s2 += wj2; s3 += wj3;
            }
        }
        float invA = 1.0f / ((lane < 16) ? s0 : s1);
        float invB = 1.0f / ((lane < 16) ? s2 : s3);
        a00 *= invA; a01 *= invA; a02 *= invA; a03 *= invA;
        a10 *= invB; a11 *= invB; a12 *= invB; a13 *= invB;
    }

    float4 hv = *(const float4*)(h + (size_t)n * HF + hf);
    float u0 = 1.0f / (1.0f + __expf(-(a00 + bu0)));
    float u1 = 1.0f / (1.0f + __expf(-(a01 + bu1)));
    float u2 = 1.0f / (1.0f + __expf(-(a02 + bu2)));
    float u3 = 1.0f / (1.0f + __expf(-(a03 + bu3)));
    float c0 = 1.0f / (1.0f + __expf(-(a10 + bc0)));
    float c1 = 1.0f / (1.0f + __expf(-(a11 + bc1)));
    float c2 = 1.0f / (1.0f + __expf(-(a12 + bc2)));
    float c3 = 1.0f / (1.0f + __expf(-(a13 + bc3)));
    float4 o;
    o.x = u0 * hv.x + (1.0f - u0) * c0;
    o.y = u1 * hv.y + (1.0f - u1) * c1;
    o.z = u2 * hv.z + (1.0f - u2) * c2;
    o.w = u3 * hv.w + (1.0f - u3) * c3;
    *(float4*)(out + (size_t)n * HF + hf) = o;
}

// ---------------- launch ----------------
extern "C" void kernel_launch(void* const* d_in, const int* in_sizes, int n_in,
                              void* d_out, int out_size) {
    const float* x         = (const float*)d_in[0];
    const float* h         = (const float*)d_in[1];
    const float* W         = (const float*)d_in[2];
    const float* attn_l    = (const float*)d_in[3];
    const float* attn_r    = (const float*)d_in[4];
    const float* conv_bias = (const float*)d_in[5];
    const float* gate_bias = (const float*)d_in[6];
    const int*   src       = (const int*)d_in[7];
    const int*   dst       = (const int*)d_in[8];
    float* out = (float*)d_out;

    zero_kernel<<<(NN + 255) / 256, 256>>>();
    count_kernel<<<(EE + 511) / 512, 512>>>(dst);
    scan12_kernel<<<NBLK, SCAN_B>>>();
    scan3_kernel<<<NBLK, SCAN_B>>>();
    scatter_kernel<<<(EE + 511) / 512, 512>>>(src, dst);

    gemm_kernel<<<dim3((NN + 127) / 128, 2), 256>>>(x, W, attn_l, attn_r);
    edge_final_kernel<<<(NN * 32 + 255) / 256, 256>>>(h, conv_bias, gate_bias, out);
}